// round 14
// baseline (speedup 1.0000x reference)
#include <cuda_runtime.h>
#include <math.h>

#define G      200
#define N0     512
#define NN     (G*N0)        // 102400
#define DEG    6
#define ET     (G*N0*DEG)    // 614400
#define EPG    (N0*DEG)      // 3072 edges per graph
#define K1     410
#define K2     328
#define K3     263
#define FIN    6
#define H      128
#define EPS    1e-5f
#define NBLK   1184          // one-wave grid for stride kernels

typedef unsigned long long u64;

// ---------------- device scratch ----------------
__device__ float g_h  [NN*H];     // conv outputs (pre-pool)
__device__ float g_hn [NN*H];     // gated pooled features
__device__ float g_agg[NN*H];     // neighbor aggregation
__device__ float g_score[NN];
__device__ int   g_map[NN];       // orig node -> current id (or -1)
__device__ int   g_perm[NN];      // current id -> orig node
__device__ int   g_sel[NN];       // current id -> local old id (pre-pool)
__device__ float g_gs[NN];        // current id -> gate scale (score)
__device__ int   g_csr_off[NN+1];
__device__ int   g_csr_src[ET];
__device__ float g_z[G*2*H];
__device__ float g_t1[G*H];
__device__ float g_t2[G*64];
__device__ float g_norm[3];

// ---------------- f32x2 helpers ----------------
__device__ __forceinline__ u64 pack2(float x, float y) {
    u64 r; asm("mov.b64 %0,{%1,%2};" : "=l"(r) : "f"(x), "f"(y)); return r;
}
__device__ __forceinline__ u64 fma2(u64 a, u64 b, u64 c) {
    u64 d; asm("fma.rn.f32x2 %0,%1,%2,%3;" : "=l"(d) : "l"(a), "l"(b), "l"(c)); return d;
}
__device__ __forceinline__ float2 unpack2(u64 v) {
    float2 f; asm("mov.b64 {%0,%1},%2;" : "=f"(f.x), "=f"(f.y) : "l"(v)); return f;
}

// ------- CSR build + map init + pw norms: one block per graph ----------------
__global__ __launch_bounds__(512) void k_csr(const int* __restrict__ ei,
                                             const float* __restrict__ pw1,
                                             const float* __restrict__ pw2,
                                             const float* __restrict__ pw3) {
    int g = blockIdx.x;
    int tid = threadIdx.x;       // 512
    __shared__ int cnt[512];
    __shared__ int scur[512];
    int e0 = g * EPG;
    int nbase = g * N0;
    cnt[tid] = 0;
    __syncthreads();
    for (int i = tid; i < EPG; i += 512)
        atomicAdd(&cnt[ei[ET + e0 + i] - nbase], 1);
    __syncthreads();
    int v = cnt[tid];
    for (int off = 1; off < 512; off <<= 1) {
        int t = (tid >= off) ? cnt[tid - off] : 0;
        __syncthreads();
        cnt[tid] += t;
        __syncthreads();
    }
    int excl = cnt[tid] - v;
    g_csr_off[nbase + tid] = e0 + excl;
    scur[tid] = excl;
    if (g == 0 && tid == 0) g_csr_off[NN] = ET;
    g_map[nbase + tid] = nbase + tid;
    g_perm[nbase + tid] = nbase + tid;
    __syncthreads();
    for (int i = tid; i < EPG; i += 512) {
        int e = e0 + i;
        int d = ei[ET + e] - nbase;
        int idx = atomicAdd(&scur[d], 1);
        g_csr_src[e0 + idx] = ei[e];
    }
    if (g == 0) {
        __shared__ float sh[128];
        const float* pws[3] = {pw1, pw2, pw3};
        #pragma unroll
        for (int j = 0; j < 3; j++) {
            if (tid < 128) { float w = pws[j][tid]; sh[tid] = w * w; }
            __syncthreads();
            for (int s = 64; s > 0; s >>= 1) {
                if (tid < s) sh[tid] += sh[tid + s];
                __syncthreads();
            }
            if (tid == 0) g_norm[j] = sqrtf(sh[0]);
            __syncthreads();
        }
    }
}

// ------- level 1: gather + conv(F_IN=6) + score; grid-stride, 2 nodes/block --
// (round-10/12 version: serial 6-thread gather — measured best)
__global__ __launch_bounds__(256) void k_conv1f(
        const float* __restrict__ x,
        const float* __restrict__ Wrel,
        const float* __restrict__ Wroot,
        const float* __restrict__ b,
        const float* __restrict__ pw) {
    int sub = threadIdx.x >> 7;        // 0..1
    int o   = threadIdx.x & 127;
    __shared__ float sx[2][FIN], sa[2][FIN], sred[2][4];
    float nrm = g_norm[0];
    for (int node = blockIdx.x * 2 + sub; node < NN; node += gridDim.x * 2) {
        if (o < FIN) {
            sx[sub][o] = x[node*FIN + o];
            int s0 = g_csr_off[node], s1 = g_csr_off[node + 1];
            float acc = 0.0f;
            for (int i = s0; i < s1; i++) acc += x[g_csr_src[i]*FIN + o];
            sa[sub][o] = acc;
        }
        __syncthreads();
        float acc = b[o];
        #pragma unroll
        for (int f = 0; f < FIN; f++)
            acc += sa[sub][f] * Wrel[o*FIN + f] + sx[sub][f] * Wroot[o*FIN + f];
        float h = fmaxf(acc, 0.0f);
        g_h[node*H + o] = h;
        float p = h * pw[o];
        #pragma unroll
        for (int s = 16; s > 0; s >>= 1) p += __shfl_xor_sync(0xffffffffu, p, s);
        if ((o & 31) == 0) sred[sub][o >> 5] = p;
        __syncthreads();
        if (o == 0)
            g_score[node] = tanhf((sred[sub][0] + sred[sub][1] +
                                   sred[sub][2] + sred[sub][3]) / nrm);
        __syncthreads();
    }
}

// ---------------- H=128 conv (64x128 tile, f32x2, dense inputs) ---------------
__global__ void k_convH(int n,
                        const float* __restrict__ Wrel,
                        const float* __restrict__ Wroot,
                        const float* __restrict__ b,
                        const float* __restrict__ pw, int which) {
    const float* X = g_hn;
    float* Y = g_h;
    __shared__ __align__(16) u64   sA[16][66];
    __shared__ __align__(16) float sB[16][132];
    int m0  = blockIdx.x * 64;
    int tid = threadIdx.x;
    int tm  = (tid >> 5) * 8;
    int tn  = (tid & 31) * 4;
    u64 acc[8][2];
    #pragma unroll
    for (int i = 0; i < 8; i++) { acc[i][0] = 0ULL; acc[i][1] = 0ULL; }

    for (int kt = 0; kt < 256; kt += 16) {
        #pragma unroll
        for (int l = 0; l < 4; l++) {
            int idx = tid + l * 256;
            int mm = idx >> 4, kk = idx & 15;
            int k = kt + kk;
            int node = m0 + mm;
            float v = 0.0f;
            if (node < n)
                v = (k < 128) ? X[node*H + k] : g_agg[node*H + (k - 128)];
            sA[kk][mm] = pack2(v, v);
        }
        #pragma unroll
        for (int l = 0; l < 8; l++) {
            int idx = tid + l * 256;
            int oo = idx >> 4, kk = idx & 15;
            int k = kt + kk;
            sB[kk][oo] = (k < 128) ? Wroot[oo*H + k] : Wrel[oo*H + (k - 128)];
        }
        __syncthreads();
        #pragma unroll
        for (int kk = 0; kk < 16; kk++) {
            ulonglong2 p0 = *(const ulonglong2*)&sA[kk][tm];
            ulonglong2 p1 = *(const ulonglong2*)&sA[kk][tm + 2];
            ulonglong2 p2 = *(const ulonglong2*)&sA[kk][tm + 4];
            ulonglong2 p3 = *(const ulonglong2*)&sA[kk][tm + 6];
            float4 bb = *(const float4*)&sB[kk][tn];
            u64 b01 = pack2(bb.x, bb.y);
            u64 b23 = pack2(bb.z, bb.w);
            u64 av[8] = {p0.x, p0.y, p1.x, p1.y, p2.x, p2.y, p3.x, p3.y};
            #pragma unroll
            for (int i = 0; i < 8; i++) {
                acc[i][0] = fma2(av[i], b01, acc[i][0]);
                acc[i][1] = fma2(av[i], b23, acc[i][1]);
            }
        }
        __syncthreads();
    }
    float4 bb4 = *(const float4*)&b[tn];
    float4 pwv = *(const float4*)&pw[tn];
    float nrm = g_norm[which];
    #pragma unroll
    for (int i = 0; i < 8; i++) {
        int node = m0 + tm + i;
        float2 v0 = unpack2(acc[i][0]);
        float2 v1 = unpack2(acc[i][1]);
        float4 o;
        o.x = fmaxf(v0.x + bb4.x, 0.0f);
        o.y = fmaxf(v0.y + bb4.y, 0.0f);
        o.z = fmaxf(v1.x + bb4.z, 0.0f);
        o.w = fmaxf(v1.y + bb4.w, 0.0f);
        float p = o.x*pwv.x + o.y*pwv.y + o.z*pwv.z + o.w*pwv.w;
        #pragma unroll
        for (int s = 16; s > 0; s >>= 1) p += __shfl_xor_sync(0xffffffffu, p, s);
        if (node < n) {
            *(float4*)&Y[node*H + tn] = o;
            if ((tid & 31) == 0) g_score[node] = tanhf(p / nrm);
        }
    }
}

// ---------------- rank: per-graph stable top-k ranks + compose + sel ----------
__global__ void k_rank(int n_per, int k) {
    int g = blockIdx.x;
    int tid = threadIdx.x;   // 512
    __shared__ float s[512];
    __shared__ int   rk[512];
    if (tid < n_per) s[tid] = g_score[g*n_per + tid];
    __syncthreads();
    if (tid < n_per) {
        float si = s[tid];
        int r = 0;
        for (int j = 0; j < n_per; j++) {
            float sj = s[j];
            r += (sj > si) || (sj == si && j < tid);
        }
        rk[tid] = r;
        if (r < k) { g_sel[g*k + r] = tid; g_gs[g*k + r] = si; }
    }
    __syncthreads();
    int orig = g*N0 + tid;
    int c = g_map[orig];
    int nc = -1;
    if (c >= 0) {
        int r = rk[c - g*n_per];
        nc = (r < k) ? (g*k + r) : -1;
    }
    g_map[orig] = nc;
    if (nc >= 0) g_perm[nc] = orig;
}

// ------- fused gated copy + readout: one block (512 thr) per graph -----------
// reads g_h[sel]*gs once; writes g_hn; accumulates max/mean into g_z.
__global__ __launch_bounds__(512) void k_poolro(int n_per, int k, int store_z) {
    int g = blockIdx.x;
    int tid = threadIdx.x;
    __shared__ float red[512];
    int f = tid & 127, part = tid >> 7;   // 4 parts, 4 node-rows in flight
    int base = g * n_per;
    float mx = -INFINITY, sm = 0.0f;
    for (int r = part; r < k; r += 4) {
        int j = g*k + r;
        float v = g_h[(base + g_sel[j])*H + f] * g_gs[j];
        g_hn[j*H + f] = v;
        mx = fmaxf(mx, v);
        sm += v;
    }
    red[tid] = mx;
    __syncthreads();
    if (part == 0) {
        float m = fmaxf(fmaxf(red[f], red[128 + f]), fmaxf(red[256 + f], red[384 + f]));
        if (store_z) g_z[g*2*H + f] = m;
        else         g_z[g*2*H + f] += m;
    }
    __syncthreads();
    red[tid] = sm;
    __syncthreads();
    if (part == 0) {
        float m = (red[f] + red[128 + f] + red[256 + f] + red[384 + f]) / (float)k;
        if (store_z) g_z[g*2*H + H + f] = m;
        else         g_z[g*2*H + H + f] += m;
    }
}

// ---- gated readout (level 3): reads g_h via sel/gs, no copy pass ------------
__global__ void k_readout3(int n_per, int k) {
    int g = blockIdx.x;
    int tid = threadIdx.x;           // 512
    __shared__ float red[512];
    int f = tid & 127, part = tid >> 7;
    float mx = -INFINITY, sm = 0.0f;
    for (int r = part; r < k; r += 4) {
        int old = g * n_per + g_sel[g*k + r];
        float v = g_h[old*H + f] * g_gs[g*k + r];
        mx = fmaxf(mx, v);
        sm += v;
    }
    red[tid] = mx;
    __syncthreads();
    if (part == 0) {
        float m = fmaxf(fmaxf(red[f], red[128 + f]), fmaxf(red[256 + f], red[384 + f]));
        g_z[g*2*H + f] += m;
    }
    __syncthreads();
    red[tid] = sm;
    __syncthreads();
    if (part == 0) {
        float m = (red[f] + red[128 + f] + red[256 + f] + red[384 + f]) / (float)k;
        g_z[g*2*H + H + f] += m;
    }
}

// ------- gather: warp-per-node, shfl-broadcast rows, float4 -------------------
__global__ __launch_bounds__(256) void k_gather(int n) {
    int slot = threadIdx.x >> 5;     // 0..7
    int lane = threadIdx.x & 31;
    for (int v = blockIdx.x * 8 + slot; v < n; v += gridDim.x * 8) {
        int u = g_perm[v];
        int start = g_csr_off[u];
        int deg   = g_csr_off[u + 1] - start;
        int row = -1;
        if (lane < deg) {
            int w = g_map[g_csr_src[start + lane]];
            row = (w >= 0) ? w * H : -1;
        }
        float4 acc = make_float4(0.f, 0.f, 0.f, 0.f);
        int m = deg < 32 ? deg : 32;
        for (int i = 0; i < m; i++) {
            int r = __shfl_sync(0xffffffffu, row, i);
            if (r >= 0) {
                float4 t = *(const float4*)&g_hn[r + lane*4];
                acc.x += t.x; acc.y += t.y; acc.z += t.z; acc.w += t.w;
            }
        }
        for (int i = 32; i < deg; i++) {          // rare tail (deg > 32)
            int w = g_map[g_csr_src[start + i]];
            if (w >= 0) {
                float4 t = *(const float4*)&g_hn[w*H + lane*4];
                acc.x += t.x; acc.y += t.y; acc.z += t.z; acc.w += t.w;
            }
        }
        *(float4*)&g_agg[v*H + lane*4] = acc;
    }
}

// ---------------- MLP head (coalesced warp-per-out) ----------------
__global__ void k_fc1(const float* __restrict__ W, const float* __restrict__ b) {
    int w = threadIdx.x >> 5, lane = threadIdx.x & 31;
    int o = blockIdx.x * 8 + w;
    int r0 = blockIdx.y * 4;
    const float* Wo = &W[o*2*H];
    float wreg[8];
    #pragma unroll
    for (int i = 0; i < 8; i++) wreg[i] = Wo[lane + 32*i];
    #pragma unroll
    for (int rr = 0; rr < 4; rr++) {
        int r = r0 + rr;
        const float* zr = &g_z[r*2*H];
        float acc = 0.0f;
        #pragma unroll
        for (int i = 0; i < 8; i++) acc += zr[lane + 32*i] * wreg[i];
        #pragma unroll
        for (int s = 16; s > 0; s >>= 1) acc += __shfl_xor_sync(0xffffffffu, acc, s);
        if (lane == 0) g_t1[r*H + o] = acc + b[o];
    }
}
__global__ void k_fc2(const float* __restrict__ W, const float* __restrict__ b) {
    int w = threadIdx.x >> 5, lane = threadIdx.x & 31;
    int o = blockIdx.x * 8 + w;
    int r0 = blockIdx.y * 8;
    const float* Wo = &W[o*H];
    float wreg[4];
    #pragma unroll
    for (int i = 0; i < 4; i++) wreg[i] = Wo[lane + 32*i];
    #pragma unroll
    for (int rr = 0; rr < 8; rr++) {
        int r = r0 + rr;
        const float* tr = &g_t1[r*H];
        float acc = 0.0f;
        #pragma unroll
        for (int i = 0; i < 4; i++) acc += tr[lane + 32*i] * wreg[i];
        #pragma unroll
        for (int s = 16; s > 0; s >>= 1) acc += __shfl_xor_sync(0xffffffffu, acc, s);
        if (lane == 0) g_t2[r*64 + o] = acc + b[o];
    }
}
__global__ void k_bn_relu(int sel, const float* __restrict__ gam,
                          const float* __restrict__ bet) {
    int F = sel ? 64 : H;
    float* Xp = sel ? g_t2 : g_t1;
    int f = blockIdx.x;
    int t = threadIdx.x;   // 64 threads
    __shared__ float sh[64];
    float s = 0.0f;
    for (int r = t; r < G; r += 64) s += Xp[r*F + f];
    sh[t] = s; __syncthreads();
    for (int st = 32; st > 0; st >>= 1) { if (t < st) sh[t] += sh[t + st]; __syncthreads(); }
    float mean = sh[0] / (float)G;
    __syncthreads();
    float v = 0.0f;
    for (int r = t; r < G; r += 64) { float d = Xp[r*F + f] - mean; v += d * d; }
    sh[t] = v; __syncthreads();
    for (int st = 32; st > 0; st >>= 1) { if (t < st) sh[t] += sh[t + st]; __syncthreads(); }
    float inv = 1.0f / sqrtf(sh[0] / (float)G + EPS);
    float gg = gam[f], bb = bet[f];
    for (int r = t; r < G; r += 64) {
        float y = (Xp[r*F + f] - mean) * inv * gg + bb;
        Xp[r*F + f] = fmaxf(y, 0.0f);
    }
}
__global__ void k_final(float* __restrict__ out,
                        const float* __restrict__ W,
                        const float* __restrict__ b) {
    int r = blockIdx.x * blockDim.x + threadIdx.x;
    if (r < G) {
        float l0 = b[0], l1 = b[1];
        for (int f = 0; f < 64; f++) {
            float v = g_t2[r*64 + f];
            l0 += v * W[f];
            l1 += v * W[64 + f];
        }
        float m = fmaxf(l0, l1);
        float e0 = expf(l0 - m), e1 = expf(l1 - m);
        float sum = e0 + e1;
        out[r*2]     = e0 / sum;
        out[r*2 + 1] = e1 / sum;
    }
}

// ---------------- launch sequence (13 launches) ----------------
extern "C" void kernel_launch(void* const* d_in, const int* in_sizes, int n_in,
                              void* d_out, int out_size) {
    const float* x      = (const float*)d_in[0];
    const int*   ei     = (const int*)  d_in[1];
    const float* Wrel1  = (const float*)d_in[2];
    const float* Wroot1 = (const float*)d_in[3];
    const float* b1     = (const float*)d_in[4];
    const float* Wrel2  = (const float*)d_in[5];
    const float* Wroot2 = (const float*)d_in[6];
    const float* b2     = (const float*)d_in[7];
    const float* Wrel3  = (const float*)d_in[8];
    const float* Wroot3 = (const float*)d_in[9];
    const float* b3     = (const float*)d_in[10];
    const float* pw1    = (const float*)d_in[11];
    const float* pw2    = (const float*)d_in[12];
    const float* pw3    = (const float*)d_in[13];
    const float* lin1_w = (const float*)d_in[14];
    const float* lin1_b = (const float*)d_in[15];
    const float* lin2_w = (const float*)d_in[16];
    const float* lin2_b = (const float*)d_in[17];
    const float* lin3_w = (const float*)d_in[18];
    const float* lin3_b = (const float*)d_in[19];
    const float* bn1_g  = (const float*)d_in[20];
    const float* bn1_b  = (const float*)d_in[21];
    const float* bn2_g  = (const float*)d_in[22];
    const float* bn2_b  = (const float*)d_in[23];
    float* out = (float*)d_out;

    // CSR build + init (single kernel)
    k_csr<<<G, 512>>>(ei, pw1, pw2, pw3);

    // level 1
    k_conv1f<<<NBLK, 256>>>(x, Wrel1, Wroot1, b1, pw1);
    k_rank<<<G, 512>>>(N0, K1);
    k_poolro<<<G, 512>>>(N0, K1, 1);
    k_gather<<<NBLK, 256>>>(G*K1);

    // level 2
    const int n2 = G * K1;
    k_convH<<<(n2 + 63)/64, 256>>>(n2, Wrel2, Wroot2, b2, pw2, 1);
    k_rank<<<G, 512>>>(K1, K2);
    k_poolro<<<G, 512>>>(K1, K2, 0);
    k_gather<<<NBLK, 256>>>(G*K2);

    // level 3
    const int n3 = G * K2;
    k_convH<<<(n3 + 63)/64, 256>>>(n3, Wrel3, Wroot3, b3, pw3, 2);
    k_rank<<<G, 512>>>(K2, K3);
    k_readout3<<<G, 512>>>(K2, K3);

    // MLP head
    k_fc1<<<dim3(16, 50), 256>>>(lin1_w, lin1_b);
    k_bn_relu<<<H, 64>>>(0, bn1_g, bn1_b);
    k_fc2<<<dim3(8, 25), 256>>>(lin2_w, lin2_b);
    k_bn_relu<<<64, 64>>>(1, bn2_g, bn2_b);
    k_final<<<(G + 127)/128, 128>>>(out, lin3_w, lin3_b);
}

// round 15
// speedup vs baseline: 1.0621x; 1.0621x over previous
#include <cuda_runtime.h>
#include <math.h>

#define G      200
#define N0     512
#define NN     (G*N0)        // 102400
#define DEG    6
#define ET     (G*N0*DEG)    // 614400
#define EPG    (N0*DEG)      // 3072 edges per graph
#define K1     410
#define K2     328
#define K3     263
#define FIN    6
#define H      128
#define EPS    1e-5f
#define NBLK   1184          // one-wave grid for stride kernels
#define RCH    16            // readout chunks per graph

typedef unsigned long long u64;

// ---------------- device scratch ----------------
__device__ float g_h  [NN*H];     // conv outputs (pre-pool)
__device__ float g_hn [NN*H];     // gated pooled features
__device__ float g_agg[NN*H];     // neighbor aggregation
__device__ float g_score[NN];
__device__ int   g_map[NN];       // orig node -> current id (or -1)
__device__ int   g_perm[NN];      // current id -> orig node
__device__ int   g_sel[NN];       // current id -> local old id (pre-pool)
__device__ float g_gs[NN];        // current id -> gate scale (score)
__device__ int   g_csr_off[NN+1];
__device__ int   g_csr_src[ET];
__device__ float g_z[G*2*H];
__device__ float g_zsum[G*H];     // per-level readout sum accumulator
__device__ unsigned g_zmax[G*H];  // per-level readout max (order-encoded)
__device__ float g_t1[G*H];
__device__ float g_t2[G*64];
__device__ float g_norm[3];

// ---------------- helpers ----------------
__device__ __forceinline__ u64 pack2(float x, float y) {
    u64 r; asm("mov.b64 %0,{%1,%2};" : "=l"(r) : "f"(x), "f"(y)); return r;
}
__device__ __forceinline__ u64 fma2(u64 a, u64 b, u64 c) {
    u64 d; asm("fma.rn.f32x2 %0,%1,%2,%3;" : "=l"(d) : "l"(a), "l"(b), "l"(c)); return d;
}
__device__ __forceinline__ float2 unpack2(u64 v) {
    float2 f; asm("mov.b64 {%0,%1},%2;" : "=f"(f.x), "=f"(f.y) : "l"(v)); return f;
}
// order-preserving float<->uint encoding (for atomicMax on any-sign floats)
__device__ __forceinline__ unsigned fenc(float x) {
    unsigned u = __float_as_uint(x);
    return (u & 0x80000000u) ? ~u : (u | 0x80000000u);
}
__device__ __forceinline__ float fdec(unsigned e) {
    unsigned u = (e & 0x80000000u) ? (e & 0x7fffffffu) : ~e;
    return __uint_as_float(u);
}

// ------- CSR build + map init + pw norms: one block per graph ----------------
__global__ __launch_bounds__(512) void k_csr(const int* __restrict__ ei,
                                             const float* __restrict__ pw1,
                                             const float* __restrict__ pw2,
                                             const float* __restrict__ pw3) {
    int g = blockIdx.x;
    int tid = threadIdx.x;       // 512
    __shared__ int cnt[512];
    __shared__ int scur[512];
    int e0 = g * EPG;
    int nbase = g * N0;
    cnt[tid] = 0;
    __syncthreads();
    for (int i = tid; i < EPG; i += 512)
        atomicAdd(&cnt[ei[ET + e0 + i] - nbase], 1);
    __syncthreads();
    int v = cnt[tid];
    for (int off = 1; off < 512; off <<= 1) {
        int t = (tid >= off) ? cnt[tid - off] : 0;
        __syncthreads();
        cnt[tid] += t;
        __syncthreads();
    }
    int excl = cnt[tid] - v;
    g_csr_off[nbase + tid] = e0 + excl;
    scur[tid] = excl;
    if (g == 0 && tid == 0) g_csr_off[NN] = ET;
    g_map[nbase + tid] = nbase + tid;
    g_perm[nbase + tid] = nbase + tid;
    __syncthreads();
    for (int i = tid; i < EPG; i += 512) {
        int e = e0 + i;
        int d = ei[ET + e] - nbase;
        int idx = atomicAdd(&scur[d], 1);
        g_csr_src[e0 + idx] = ei[e];
    }
    if (g == 0) {
        __shared__ float sh[128];
        const float* pws[3] = {pw1, pw2, pw3};
        #pragma unroll
        for (int j = 0; j < 3; j++) {
            if (tid < 128) { float w = pws[j][tid]; sh[tid] = w * w; }
            __syncthreads();
            for (int s = 64; s > 0; s >>= 1) {
                if (tid < s) sh[tid] += sh[tid + s];
                __syncthreads();
            }
            if (tid == 0) g_norm[j] = sqrtf(sh[0]);
            __syncthreads();
        }
    }
}

// ------- level 1: gather + conv(F_IN=6) + score; grid-stride, 2 nodes/block --
__global__ __launch_bounds__(256) void k_conv1f(
        const float* __restrict__ x,
        const float* __restrict__ Wrel,
        const float* __restrict__ Wroot,
        const float* __restrict__ b,
        const float* __restrict__ pw) {
    int sub = threadIdx.x >> 7;        // 0..1
    int o   = threadIdx.x & 127;
    __shared__ float sx[2][FIN], sa[2][FIN], sred[2][4];
    float nrm = g_norm[0];
    for (int node = blockIdx.x * 2 + sub; node < NN; node += gridDim.x * 2) {
        if (o < FIN) {
            sx[sub][o] = x[node*FIN + o];
            int s0 = g_csr_off[node], s1 = g_csr_off[node + 1];
            float acc = 0.0f;
            for (int i = s0; i < s1; i++) acc += x[g_csr_src[i]*FIN + o];
            sa[sub][o] = acc;
        }
        __syncthreads();
        float acc = b[o];
        #pragma unroll
        for (int f = 0; f < FIN; f++)
            acc += sa[sub][f] * Wrel[o*FIN + f] + sx[sub][f] * Wroot[o*FIN + f];
        float h = fmaxf(acc, 0.0f);
        g_h[node*H + o] = h;
        float p = h * pw[o];
        #pragma unroll
        for (int s = 16; s > 0; s >>= 1) p += __shfl_xor_sync(0xffffffffu, p, s);
        if ((o & 31) == 0) sred[sub][o >> 5] = p;
        __syncthreads();
        if (o == 0)
            g_score[node] = tanhf((sred[sub][0] + sred[sub][1] +
                                   sred[sub][2] + sred[sub][3]) / nrm);
        __syncthreads();
    }
}

// ---------------- H=128 conv (64x128 tile, f32x2, dense inputs) ---------------
__global__ void k_convH(int n,
                        const float* __restrict__ Wrel,
                        const float* __restrict__ Wroot,
                        const float* __restrict__ b,
                        const float* __restrict__ pw, int which) {
    const float* X = g_hn;
    float* Y = g_h;
    __shared__ __align__(16) u64   sA[16][66];
    __shared__ __align__(16) float sB[16][132];
    int m0  = blockIdx.x * 64;
    int tid = threadIdx.x;
    int tm  = (tid >> 5) * 8;
    int tn  = (tid & 31) * 4;
    u64 acc[8][2];
    #pragma unroll
    for (int i = 0; i < 8; i++) { acc[i][0] = 0ULL; acc[i][1] = 0ULL; }

    for (int kt = 0; kt < 256; kt += 16) {
        #pragma unroll
        for (int l = 0; l < 4; l++) {
            int idx = tid + l * 256;
            int mm = idx >> 4, kk = idx & 15;
            int k = kt + kk;
            int node = m0 + mm;
            float v = 0.0f;
            if (node < n)
                v = (k < 128) ? X[node*H + k] : g_agg[node*H + (k - 128)];
            sA[kk][mm] = pack2(v, v);
        }
        #pragma unroll
        for (int l = 0; l < 8; l++) {
            int idx = tid + l * 256;
            int oo = idx >> 4, kk = idx & 15;
            int k = kt + kk;
            sB[kk][oo] = (k < 128) ? Wroot[oo*H + k] : Wrel[oo*H + (k - 128)];
        }
        __syncthreads();
        #pragma unroll
        for (int kk = 0; kk < 16; kk++) {
            ulonglong2 p0 = *(const ulonglong2*)&sA[kk][tm];
            ulonglong2 p1 = *(const ulonglong2*)&sA[kk][tm + 2];
            ulonglong2 p2 = *(const ulonglong2*)&sA[kk][tm + 4];
            ulonglong2 p3 = *(const ulonglong2*)&sA[kk][tm + 6];
            float4 bb = *(const float4*)&sB[kk][tn];
            u64 b01 = pack2(bb.x, bb.y);
            u64 b23 = pack2(bb.z, bb.w);
            u64 av[8] = {p0.x, p0.y, p1.x, p1.y, p2.x, p2.y, p3.x, p3.y};
            #pragma unroll
            for (int i = 0; i < 8; i++) {
                acc[i][0] = fma2(av[i], b01, acc[i][0]);
                acc[i][1] = fma2(av[i], b23, acc[i][1]);
            }
        }
        __syncthreads();
    }
    float4 bb4 = *(const float4*)&b[tn];
    float4 pwv = *(const float4*)&pw[tn];
    float nrm = g_norm[which];
    #pragma unroll
    for (int i = 0; i < 8; i++) {
        int node = m0 + tm + i;
        float2 v0 = unpack2(acc[i][0]);
        float2 v1 = unpack2(acc[i][1]);
        float4 o;
        o.x = fmaxf(v0.x + bb4.x, 0.0f);
        o.y = fmaxf(v0.y + bb4.y, 0.0f);
        o.z = fmaxf(v1.x + bb4.z, 0.0f);
        o.w = fmaxf(v1.y + bb4.w, 0.0f);
        float p = o.x*pwv.x + o.y*pwv.y + o.z*pwv.z + o.w*pwv.w;
        #pragma unroll
        for (int s = 16; s > 0; s >>= 1) p += __shfl_xor_sync(0xffffffffu, p, s);
        if (node < n) {
            *(float4*)&Y[node*H + tn] = o;
            if ((tid & 31) == 0) g_score[node] = tanhf(p / nrm);
        }
    }
}

// ------ rank: stable top-k ranks + compose + sel + init readout accum --------
__global__ void k_rank(int n_per, int k) {
    int g = blockIdx.x;
    int tid = threadIdx.x;   // 512
    __shared__ float s[512];
    __shared__ int   rk[512];
    if (tid < n_per) s[tid] = g_score[g*n_per + tid];
    // init this graph's readout accumulators
    if (tid < H) {
        g_zsum[g*H + tid] = 0.0f;
        g_zmax[g*H + tid] = fenc(-INFINITY);
    }
    __syncthreads();
    if (tid < n_per) {
        float si = s[tid];
        int r = 0;
        for (int j = 0; j < n_per; j++) {
            float sj = s[j];
            r += (sj > si) || (sj == si && j < tid);
        }
        rk[tid] = r;
        if (r < k) { g_sel[g*k + r] = tid; g_gs[g*k + r] = si; }
    }
    __syncthreads();
    int orig = g*N0 + tid;
    int c = g_map[orig];
    int nc = -1;
    if (c >= 0) {
        int r = rk[c - g*n_per];
        nc = (r < k) ? (g*k + r) : -1;
    }
    g_map[orig] = nc;
    if (nc >= 0) g_perm[nc] = orig;
}

// ------- fused gated copy + chunked readout: grid (G, RCH), 128 thr ----------
__global__ __launch_bounds__(128) void k_poolcr(int n_per, int k) {
    int g = blockIdx.x, c = blockIdx.y;
    int f = threadIdx.x;
    int base = g * n_per;
    float mx = -INFINITY, sm = 0.0f;
    for (int r = c; r < k; r += RCH) {
        int j = g*k + r;
        float v = g_h[(base + g_sel[j])*H + f] * g_gs[j];
        g_hn[j*H + f] = v;
        mx = fmaxf(mx, v);
        sm += v;
    }
    atomicMax(&g_zmax[g*H + f], fenc(mx));
    atomicAdd(&g_zsum[g*H + f], sm);
}

// ------- level-3 chunked gated readout (no copy): grid (G, RCH) --------------
__global__ __launch_bounds__(128) void k_ro3(int n_per, int k) {
    int g = blockIdx.x, c = blockIdx.y;
    int f = threadIdx.x;
    int base = g * n_per;
    float mx = -INFINITY, sm = 0.0f;
    for (int r = c; r < k; r += RCH) {
        int j = g*k + r;
        float v = g_h[(base + g_sel[j])*H + f] * g_gs[j];
        mx = fmaxf(mx, v);
        sm += v;
    }
    atomicMax(&g_zmax[g*H + f], fenc(mx));
    atomicAdd(&g_zsum[g*H + f], sm);
}

// ------- finalize readout into g_z --------------------------------------------
__global__ void k_zfin(int k, int store_z) {
    int g = blockIdx.x, f = threadIdx.x;   // 128
    float mx = fdec(g_zmax[g*H + f]);
    float mn = g_zsum[g*H + f] / (float)k;
    if (store_z) { g_z[g*2*H + f] = mx;  g_z[g*2*H + H + f] = mn; }
    else         { g_z[g*2*H + f] += mx; g_z[g*2*H + H + f] += mn; }
}

// ------- gather: warp-per-node, shfl-broadcast rows, float4 -------------------
__global__ __launch_bounds__(256) void k_gather(int n) {
    int slot = threadIdx.x >> 5;     // 0..7
    int lane = threadIdx.x & 31;
    for (int v = blockIdx.x * 8 + slot; v < n; v += gridDim.x * 8) {
        int u = g_perm[v];
        int start = g_csr_off[u];
        int deg   = g_csr_off[u + 1] - start;
        int row = -1;
        if (lane < deg) {
            int w = g_map[g_csr_src[start + lane]];
            row = (w >= 0) ? w * H : -1;
        }
        float4 acc = make_float4(0.f, 0.f, 0.f, 0.f);
        int m = deg < 32 ? deg : 32;
        for (int i = 0; i < m; i++) {
            int r = __shfl_sync(0xffffffffu, row, i);
            if (r >= 0) {
                float4 t = *(const float4*)&g_hn[r + lane*4];
                acc.x += t.x; acc.y += t.y; acc.z += t.z; acc.w += t.w;
            }
        }
        for (int i = 32; i < deg; i++) {          // rare tail (deg > 32)
            int w = g_map[g_csr_src[start + i]];
            if (w >= 0) {
                float4 t = *(const float4*)&g_hn[w*H + lane*4];
                acc.x += t.x; acc.y += t.y; acc.z += t.z; acc.w += t.w;
            }
        }
        *(float4*)&g_agg[v*H + lane*4] = acc;
    }
}

// ---------------- MLP head (coalesced warp-per-out) ----------------
__global__ void k_fc1(const float* __restrict__ W, const float* __restrict__ b) {
    int w = threadIdx.x >> 5, lane = threadIdx.x & 31;
    int o = blockIdx.x * 8 + w;
    int r0 = blockIdx.y * 4;
    const float* Wo = &W[o*2*H];
    float wreg[8];
    #pragma unroll
    for (int i = 0; i < 8; i++) wreg[i] = Wo[lane + 32*i];
    #pragma unroll
    for (int rr = 0; rr < 4; rr++) {
        int r = r0 + rr;
        const float* zr = &g_z[r*2*H];
        float acc = 0.0f;
        #pragma unroll
        for (int i = 0; i < 8; i++) acc += zr[lane + 32*i] * wreg[i];
        #pragma unroll
        for (int s = 16; s > 0; s >>= 1) acc += __shfl_xor_sync(0xffffffffu, acc, s);
        if (lane == 0) g_t1[r*H + o] = acc + b[o];
    }
}
__global__ void k_fc2(const float* __restrict__ W, const float* __restrict__ b) {
    int w = threadIdx.x >> 5, lane = threadIdx.x & 31;
    int o = blockIdx.x * 8 + w;
    int r0 = blockIdx.y * 8;
    const float* Wo = &W[o*H];
    float wreg[4];
    #pragma unroll
    for (int i = 0; i < 4; i++) wreg[i] = Wo[lane + 32*i];
    #pragma unroll
    for (int rr = 0; rr < 8; rr++) {
        int r = r0 + rr;
        const float* tr = &g_t1[r*H];
        float acc = 0.0f;
        #pragma unroll
        for (int i = 0; i < 4; i++) acc += tr[lane + 32*i] * wreg[i];
        #pragma unroll
        for (int s = 16; s > 0; s >>= 1) acc += __shfl_xor_sync(0xffffffffu, acc, s);
        if (lane == 0) g_t2[r*64 + o] = acc + b[o];
    }
}
__global__ void k_bn_relu(int sel, const float* __restrict__ gam,
                          const float* __restrict__ bet) {
    int F = sel ? 64 : H;
    float* Xp = sel ? g_t2 : g_t1;
    int f = blockIdx.x;
    int t = threadIdx.x;   // 64 threads
    __shared__ float sh[64];
    float s = 0.0f;
    for (int r = t; r < G; r += 64) s += Xp[r*F + f];
    sh[t] = s; __syncthreads();
    for (int st = 32; st > 0; st >>= 1) { if (t < st) sh[t] += sh[t + st]; __syncthreads(); }
    float mean = sh[0] / (float)G;
    __syncthreads();
    float v = 0.0f;
    for (int r = t; r < G; r += 64) { float d = Xp[r*F + f] - mean; v += d * d; }
    sh[t] = v; __syncthreads();
    for (int st = 32; st > 0; st >>= 1) { if (t < st) sh[t] += sh[t + st]; __syncthreads(); }
    float inv = 1.0f / sqrtf(sh[0] / (float)G + EPS);
    float gg = gam[f], bb = bet[f];
    for (int r = t; r < G; r += 64) {
        float y = (Xp[r*F + f] - mean) * inv * gg + bb;
        Xp[r*F + f] = fmaxf(y, 0.0f);
    }
}
__global__ void k_final(float* __restrict__ out,
                        const float* __restrict__ W,
                        const float* __restrict__ b) {
    int r = blockIdx.x * blockDim.x + threadIdx.x;
    if (r < G) {
        float l0 = b[0], l1 = b[1];
        for (int f = 0; f < 64; f++) {
            float v = g_t2[r*64 + f];
            l0 += v * W[f];
            l1 += v * W[64 + f];
        }
        float m = fmaxf(l0, l1);
        float e0 = expf(l0 - m), e1 = expf(l1 - m);
        float sum = e0 + e1;
        out[r*2]     = e0 / sum;
        out[r*2 + 1] = e1 / sum;
    }
}

// ---------------- launch sequence ----------------
extern "C" void kernel_launch(void* const* d_in, const int* in_sizes, int n_in,
                              void* d_out, int out_size) {
    const float* x      = (const float*)d_in[0];
    const int*   ei     = (const int*)  d_in[1];
    const float* Wrel1  = (const float*)d_in[2];
    const float* Wroot1 = (const float*)d_in[3];
    const float* b1     = (const float*)d_in[4];
    const float* Wrel2  = (const float*)d_in[5];
    const float* Wroot2 = (const float*)d_in[6];
    const float* b2     = (const float*)d_in[7];
    const float* Wrel3  = (const float*)d_in[8];
    const float* Wroot3 = (const float*)d_in[9];
    const float* b3     = (const float*)d_in[10];
    const float* pw1    = (const float*)d_in[11];
    const float* pw2    = (const float*)d_in[12];
    const float* pw3    = (const float*)d_in[13];
    const float* lin1_w = (const float*)d_in[14];
    const float* lin1_b = (const float*)d_in[15];
    const float* lin2_w = (const float*)d_in[16];
    const float* lin2_b = (const float*)d_in[17];
    const float* lin3_w = (const float*)d_in[18];
    const float* lin3_b = (const float*)d_in[19];
    const float* bn1_g  = (const float*)d_in[20];
    const float* bn1_b  = (const float*)d_in[21];
    const float* bn2_g  = (const float*)d_in[22];
    const float* bn2_b  = (const float*)d_in[23];
    float* out = (float*)d_out;

    // CSR build + init (single kernel)
    k_csr<<<G, 512>>>(ei, pw1, pw2, pw3);

    // level 1
    k_conv1f<<<NBLK, 256>>>(x, Wrel1, Wroot1, b1, pw1);
    k_rank<<<G, 512>>>(N0, K1);
    k_poolcr<<<dim3(G, RCH), 128>>>(N0, K1);
    k_zfin<<<G, 128>>>(K1, 1);
    k_gather<<<NBLK, 256>>>(G*K1);

    // level 2
    const int n2 = G * K1;
    k_convH<<<(n2 + 63)/64, 256>>>(n2, Wrel2, Wroot2, b2, pw2, 1);
    k_rank<<<G, 512>>>(K1, K2);
    k_poolcr<<<dim3(G, RCH), 128>>>(K1, K2);
    k_zfin<<<G, 128>>>(K2, 0);
    k_gather<<<NBLK, 256>>>(G*K2);

    // level 3
    const int n3 = G * K2;
    k_convH<<<(n3 + 63)/64, 256>>>(n3, Wrel3, Wroot3, b3, pw3, 2);
    k_rank<<<G, 512>>>(K2, K3);
    k_ro3<<<dim3(G, RCH), 128>>>(K2, K3);
    k_zfin<<<G, 128>>>(K3, 0);

    // MLP head
    k_fc1<<<dim3(16, 50), 256>>>(lin1_w, lin1_b);
    k_bn_relu<<<H, 64>>>(0, bn1_g, bn1_b);
    k_fc2<<<dim3(8, 25), 256>>>(lin2_w, lin2_b);
    k_bn_relu<<<64, 64>>>(1, bn2_g, bn2_b);
    k_final<<<(G + 127)/128, 128>>>(out, lin3_w, lin3_b);
}

// round 16
// speedup vs baseline: 1.1072x; 1.0425x over previous
#include <cuda_runtime.h>
#include <math.h>

#define G      200
#define N0     512
#define NN     (G*N0)        // 102400
#define DEG    6
#define ET     (G*N0*DEG)    // 614400
#define EPG    (N0*DEG)      // 3072 edges per graph
#define K1     410
#define K2     328
#define K3     263
#define FIN    6
#define H      128
#define EPS    1e-5f
#define NBLK   1184          // one-wave grid for stride kernels
#define RCH    16            // readout chunks per graph

typedef unsigned long long u64;

// ---------------- device scratch ----------------
__device__ float g_h  [NN*H];     // conv outputs (pre-pool)
__device__ float g_hn [NN*H];     // gated pooled features
__device__ float g_agg[NN*H];     // neighbor aggregation
__device__ float g_score[NN];
__device__ int   g_map[NN];       // orig node -> current id (or -1)
__device__ int   g_perm[NN];      // current id -> orig node
__device__ int   g_sel[NN];       // current id -> local old id (pre-pool)
__device__ float g_gs[NN];        // current id -> gate scale (score)
__device__ int   g_csr_off[NN+1];
__device__ int   g_csr_src[ET];
__device__ float g_z[G*2*H];
__device__ float g_zsum[G*H];     // per-level readout sum accumulator
__device__ unsigned g_zmax[G*H];  // per-level readout max (order-encoded)
__device__ float g_t1[G*H];
__device__ float g_t2[G*64];
__device__ float g_norm[3];

// ---------------- helpers ----------------
__device__ __forceinline__ u64 pack2(float x, float y) {
    u64 r; asm("mov.b64 %0,{%1,%2};" : "=l"(r) : "f"(x), "f"(y)); return r;
}
__device__ __forceinline__ u64 fma2(u64 a, u64 b, u64 c) {
    u64 d; asm("fma.rn.f32x2 %0,%1,%2,%3;" : "=l"(d) : "l"(a), "l"(b), "l"(c)); return d;
}
__device__ __forceinline__ float2 unpack2(u64 v) {
    float2 f; asm("mov.b64 {%0,%1},%2;" : "=f"(f.x), "=f"(f.y) : "l"(v)); return f;
}
__device__ __forceinline__ unsigned fenc(float x) {
    unsigned u = __float_as_uint(x);
    return (u & 0x80000000u) ? ~u : (u | 0x80000000u);
}
__device__ __forceinline__ float fdec(unsigned e) {
    unsigned u = (e & 0x80000000u) ? (e & 0x7fffffffu) : ~e;
    return __uint_as_float(u);
}

// ------- CSR build + map init + pw norms: one block per graph ----------------
__global__ __launch_bounds__(512) void k_csr(const int* __restrict__ ei,
                                             const float* __restrict__ pw1,
                                             const float* __restrict__ pw2,
                                             const float* __restrict__ pw3) {
    int g = blockIdx.x;
    int tid = threadIdx.x;       // 512
    __shared__ int cnt[512];
    __shared__ int scur[512];
    int e0 = g * EPG;
    int nbase = g * N0;
    cnt[tid] = 0;
    __syncthreads();
    for (int i = tid; i < EPG; i += 512)
        atomicAdd(&cnt[ei[ET + e0 + i] - nbase], 1);
    __syncthreads();
    int v = cnt[tid];
    for (int off = 1; off < 512; off <<= 1) {
        int t = (tid >= off) ? cnt[tid - off] : 0;
        __syncthreads();
        cnt[tid] += t;
        __syncthreads();
    }
    int excl = cnt[tid] - v;
    g_csr_off[nbase + tid] = e0 + excl;
    scur[tid] = excl;
    if (g == 0 && tid == 0) g_csr_off[NN] = ET;
    g_map[nbase + tid] = nbase + tid;
    g_perm[nbase + tid] = nbase + tid;
    __syncthreads();
    for (int i = tid; i < EPG; i += 512) {
        int e = e0 + i;
        int d = ei[ET + e] - nbase;
        int idx = atomicAdd(&scur[d], 1);
        g_csr_src[e0 + idx] = ei[e];
    }
    if (g == 0) {
        __shared__ float sh[128];
        const float* pws[3] = {pw1, pw2, pw3};
        #pragma unroll
        for (int j = 0; j < 3; j++) {
            if (tid < 128) { float w = pws[j][tid]; sh[tid] = w * w; }
            __syncthreads();
            for (int s = 64; s > 0; s >>= 1) {
                if (tid < s) sh[tid] += sh[tid + s];
                __syncthreads();
            }
            if (tid == 0) g_norm[j] = sqrtf(sh[0]);
            __syncthreads();
        }
    }
}

// ------- level 1: gather + conv(F_IN=6) + score; grid-stride, 2 nodes/block --
__global__ __launch_bounds__(256) void k_conv1f(
        const float* __restrict__ x,
        const float* __restrict__ Wrel,
        const float* __restrict__ Wroot,
        const float* __restrict__ b,
        const float* __restrict__ pw) {
    int sub = threadIdx.x >> 7;        // 0..1
    int o   = threadIdx.x & 127;
    __shared__ float sx[2][FIN], sa[2][FIN], sred[2][4];
    float nrm = g_norm[0];
    for (int node = blockIdx.x * 2 + sub; node < NN; node += gridDim.x * 2) {
        if (o < FIN) {
            sx[sub][o] = x[node*FIN + o];
            int s0 = g_csr_off[node], s1 = g_csr_off[node + 1];
            float acc = 0.0f;
            for (int i = s0; i < s1; i++) acc += x[g_csr_src[i]*FIN + o];
            sa[sub][o] = acc;
        }
        __syncthreads();
        float acc = b[o];
        #pragma unroll
        for (int f = 0; f < FIN; f++)
            acc += sa[sub][f] * Wrel[o*FIN + f] + sx[sub][f] * Wroot[o*FIN + f];
        float h = fmaxf(acc, 0.0f);
        g_h[node*H + o] = h;
        float p = h * pw[o];
        #pragma unroll
        for (int s = 16; s > 0; s >>= 1) p += __shfl_xor_sync(0xffffffffu, p, s);
        if ((o & 31) == 0) sred[sub][o >> 5] = p;
        __syncthreads();
        if (o == 0)
            g_score[node] = tanhf((sred[sub][0] + sred[sub][1] +
                                   sred[sub][2] + sred[sub][3]) / nrm);
        __syncthreads();
    }
}

// ---------------- H=128 conv (64x128 tile, f32x2, dense inputs) ---------------
__global__ void k_convH(int n,
                        const float* __restrict__ Wrel,
                        const float* __restrict__ Wroot,
                        const float* __restrict__ b,
                        const float* __restrict__ pw, int which) {
    const float* X = g_hn;
    float* Y = g_h;
    __shared__ __align__(16) u64   sA[16][66];
    __shared__ __align__(16) float sB[16][132];
    int m0  = blockIdx.x * 64;
    int tid = threadIdx.x;
    int tm  = (tid >> 5) * 8;
    int tn  = (tid & 31) * 4;
    u64 acc[8][2];
    #pragma unroll
    for (int i = 0; i < 8; i++) { acc[i][0] = 0ULL; acc[i][1] = 0ULL; }

    for (int kt = 0; kt < 256; kt += 16) {
        #pragma unroll
        for (int l = 0; l < 4; l++) {
            int idx = tid + l * 256;
            int mm = idx >> 4, kk = idx & 15;
            int k = kt + kk;
            int node = m0 + mm;
            float v = 0.0f;
            if (node < n)
                v = (k < 128) ? X[node*H + k] : g_agg[node*H + (k - 128)];
            sA[kk][mm] = pack2(v, v);
        }
        #pragma unroll
        for (int l = 0; l < 8; l++) {
            int idx = tid + l * 256;
            int oo = idx >> 4, kk = idx & 15;
            int k = kt + kk;
            sB[kk][oo] = (k < 128) ? Wroot[oo*H + k] : Wrel[oo*H + (k - 128)];
        }
        __syncthreads();
        #pragma unroll
        for (int kk = 0; kk < 16; kk++) {
            ulonglong2 p0 = *(const ulonglong2*)&sA[kk][tm];
            ulonglong2 p1 = *(const ulonglong2*)&sA[kk][tm + 2];
            ulonglong2 p2 = *(const ulonglong2*)&sA[kk][tm + 4];
            ulonglong2 p3 = *(const ulonglong2*)&sA[kk][tm + 6];
            float4 bb = *(const float4*)&sB[kk][tn];
            u64 b01 = pack2(bb.x, bb.y);
            u64 b23 = pack2(bb.z, bb.w);
            u64 av[8] = {p0.x, p0.y, p1.x, p1.y, p2.x, p2.y, p3.x, p3.y};
            #pragma unroll
            for (int i = 0; i < 8; i++) {
                acc[i][0] = fma2(av[i], b01, acc[i][0]);
                acc[i][1] = fma2(av[i], b23, acc[i][1]);
            }
        }
        __syncthreads();
    }
    float4 bb4 = *(const float4*)&b[tn];
    float4 pwv = *(const float4*)&pw[tn];
    float nrm = g_norm[which];
    #pragma unroll
    for (int i = 0; i < 8; i++) {
        int node = m0 + tm + i;
        float2 v0 = unpack2(acc[i][0]);
        float2 v1 = unpack2(acc[i][1]);
        float4 o;
        o.x = fmaxf(v0.x + bb4.x, 0.0f);
        o.y = fmaxf(v0.y + bb4.y, 0.0f);
        o.z = fmaxf(v1.x + bb4.z, 0.0f);
        o.w = fmaxf(v1.y + bb4.w, 0.0f);
        float p = o.x*pwv.x + o.y*pwv.y + o.z*pwv.z + o.w*pwv.w;
        #pragma unroll
        for (int s = 16; s > 0; s >>= 1) p += __shfl_xor_sync(0xffffffffu, p, s);
        if (node < n) {
            *(float4*)&Y[node*H + tn] = o;
            if ((tid & 31) == 0) g_score[node] = tanhf(p / nrm);
        }
    }
}

// ------ rank: stable top-k ranks + compose + sel + init readout accum --------
__global__ void k_rank(int n_per, int k) {
    int g = blockIdx.x;
    int tid = threadIdx.x;   // 512
    __shared__ float s[512];
    __shared__ int   rk[512];
    if (tid < n_per) s[tid] = g_score[g*n_per + tid];
    if (tid < H) {
        g_zsum[g*H + tid] = 0.0f;
        g_zmax[g*H + tid] = fenc(-INFINITY);
    }
    __syncthreads();
    if (tid < n_per) {
        float si = s[tid];
        int r = 0;
        for (int j = 0; j < n_per; j++) {
            float sj = s[j];
            r += (sj > si) || (sj == si && j < tid);
        }
        rk[tid] = r;
        if (r < k) { g_sel[g*k + r] = tid; g_gs[g*k + r] = si; }
    }
    __syncthreads();
    int orig = g*N0 + tid;
    int c = g_map[orig];
    int nc = -1;
    if (c >= 0) {
        int r = rk[c - g*n_per];
        nc = (r < k) ? (g*k + r) : -1;
    }
    g_map[orig] = nc;
    if (nc >= 0) g_perm[nc] = orig;
}

// ------- gated copy: warp-per-node, float4; 8 nodes per 256-thr block iter ---
__global__ __launch_bounds__(256) void k_copy(int n_per, int k, int n) {
    int slot = threadIdx.x >> 5;     // 0..7
    int lane = threadIdx.x & 31;
    for (int j = blockIdx.x * 8 + slot; j < n; j += gridDim.x * 8) {
        int g = j / k;
        int old = g * n_per + g_sel[j];
        float gs = g_gs[j];
        float4 v = *(const float4*)&g_h[old*H + lane*4];
        v.x *= gs; v.y *= gs; v.z *= gs; v.w *= gs;
        *(float4*)&g_hn[j*H + lane*4] = v;
    }
}

// ------- chunked dense readout: grid (G, RCH), 128 thr; reads g_hn -----------
__global__ __launch_bounds__(128) void k_rochunk(int k) {
    int g = blockIdx.x, c = blockIdx.y;
    int f = threadIdx.x;
    float mx = -INFINITY, sm = 0.0f;
    for (int r = c; r < k; r += RCH) {
        float v = g_hn[(g*k + r)*H + f];
        mx = fmaxf(mx, v);
        sm += v;
    }
    atomicMax(&g_zmax[g*H + f], fenc(mx));
    atomicAdd(&g_zsum[g*H + f], sm);
}

// ------- level-3 chunked gated readout (no copy): grid (G, RCH) --------------
__global__ __launch_bounds__(128) void k_ro3(int n_per, int k) {
    int g = blockIdx.x, c = blockIdx.y;
    int f = threadIdx.x;
    int base = g * n_per;
    float mx = -INFINITY, sm = 0.0f;
    for (int r = c; r < k; r += RCH) {
        int j = g*k + r;
        float v = g_h[(base + g_sel[j])*H + f] * g_gs[j];
        mx = fmaxf(mx, v);
        sm += v;
    }
    atomicMax(&g_zmax[g*H + f], fenc(mx));
    atomicAdd(&g_zsum[g*H + f], sm);
}

// ------- finalize readout into g_z --------------------------------------------
__global__ void k_zfin(int k, int store_z) {
    int g = blockIdx.x, f = threadIdx.x;   // 128
    float mx = fdec(g_zmax[g*H + f]);
    float mn = g_zsum[g*H + f] / (float)k;
    if (store_z) { g_z[g*2*H + f] = mx;  g_z[g*2*H + H + f] = mn; }
    else         { g_z[g*2*H + f] += mx; g_z[g*2*H + H + f] += mn; }
}

// ------- gather: warp-per-node, shfl-broadcast rows, float4 -------------------
__global__ __launch_bounds__(256) void k_gather(int n) {
    int slot = threadIdx.x >> 5;     // 0..7
    int lane = threadIdx.x & 31;
    for (int v = blockIdx.x * 8 + slot; v < n; v += gridDim.x * 8) {
        int u = g_perm[v];
        int start = g_csr_off[u];
        int deg   = g_csr_off[u + 1] - start;
        int row = -1;
        if (lane < deg) {
            int w = g_map[g_csr_src[start + lane]];
            row = (w >= 0) ? w * H : -1;
        }
        float4 acc = make_float4(0.f, 0.f, 0.f, 0.f);
        int m = deg < 32 ? deg : 32;
        for (int i = 0; i < m; i++) {
            int r = __shfl_sync(0xffffffffu, row, i);
            if (r >= 0) {
                float4 t = *(const float4*)&g_hn[r + lane*4];
                acc.x += t.x; acc.y += t.y; acc.z += t.z; acc.w += t.w;
            }
        }
        for (int i = 32; i < deg; i++) {          // rare tail (deg > 32)
            int w = g_map[g_csr_src[start + i]];
            if (w >= 0) {
                float4 t = *(const float4*)&g_hn[w*H + lane*4];
                acc.x += t.x; acc.y += t.y; acc.z += t.z; acc.w += t.w;
            }
        }
        *(float4*)&g_agg[v*H + lane*4] = acc;
    }
}

// ---------------- MLP head (coalesced warp-per-out) ----------------
__global__ void k_fc1(const float* __restrict__ W, const float* __restrict__ b) {
    int w = threadIdx.x >> 5, lane = threadIdx.x & 31;
    int o = blockIdx.x * 8 + w;
    int r0 = blockIdx.y * 4;
    const float* Wo = &W[o*2*H];
    float wreg[8];
    #pragma unroll
    for (int i = 0; i < 8; i++) wreg[i] = Wo[lane + 32*i];
    #pragma unroll
    for (int rr = 0; rr < 4; rr++) {
        int r = r0 + rr;
        const float* zr = &g_z[r*2*H];
        float acc = 0.0f;
        #pragma unroll
        for (int i = 0; i < 8; i++) acc += zr[lane + 32*i] * wreg[i];
        #pragma unroll
        for (int s = 16; s > 0; s >>= 1) acc += __shfl_xor_sync(0xffffffffu, acc, s);
        if (lane == 0) g_t1[r*H + o] = acc + b[o];
    }
}
__global__ void k_fc2(const float* __restrict__ W, const float* __restrict__ b) {
    int w = threadIdx.x >> 5, lane = threadIdx.x & 31;
    int o = blockIdx.x * 8 + w;
    int r0 = blockIdx.y * 8;
    const float* Wo = &W[o*H];
    float wreg[4];
    #pragma unroll
    for (int i = 0; i < 4; i++) wreg[i] = Wo[lane + 32*i];
    #pragma unroll
    for (int rr = 0; rr < 8; rr++) {
        int r = r0 + rr;
        const float* tr = &g_t1[r*H];
        float acc = 0.0f;
        #pragma unroll
        for (int i = 0; i < 4; i++) acc += tr[lane + 32*i] * wreg[i];
        #pragma unroll
        for (int s = 16; s > 0; s >>= 1) acc += __shfl_xor_sync(0xffffffffu, acc, s);
        if (lane == 0) g_t2[r*64 + o] = acc + b[o];
    }
}
__global__ void k_bn_relu(int sel, const float* __restrict__ gam,
                          const float* __restrict__ bet) {
    int F = sel ? 64 : H;
    float* Xp = sel ? g_t2 : g_t1;
    int f = blockIdx.x;
    int t = threadIdx.x;   // 64 threads
    __shared__ float sh[64];
    float s = 0.0f;
    for (int r = t; r < G; r += 64) s += Xp[r*F + f];
    sh[t] = s; __syncthreads();
    for (int st = 32; st > 0; st >>= 1) { if (t < st) sh[t] += sh[t + st]; __syncthreads(); }
    float mean = sh[0] / (float)G;
    __syncthreads();
    float v = 0.0f;
    for (int r = t; r < G; r += 64) { float d = Xp[r*F + f] - mean; v += d * d; }
    sh[t] = v; __syncthreads();
    for (int st = 32; st > 0; st >>= 1) { if (t < st) sh[t] += sh[t + st]; __syncthreads(); }
    float inv = 1.0f / sqrtf(sh[0] / (float)G + EPS);
    float gg = gam[f], bb = bet[f];
    for (int r = t; r < G; r += 64) {
        float y = (Xp[r*F + f] - mean) * inv * gg + bb;
        Xp[r*F + f] = fmaxf(y, 0.0f);
    }
}
__global__ void k_final(float* __restrict__ out,
                        const float* __restrict__ W,
                        const float* __restrict__ b) {
    int r = blockIdx.x * blockDim.x + threadIdx.x;
    if (r < G) {
        float l0 = b[0], l1 = b[1];
        for (int f = 0; f < 64; f++) {
            float v = g_t2[r*64 + f];
            l0 += v * W[f];
            l1 += v * W[64 + f];
        }
        float m = fmaxf(l0, l1);
        float e0 = expf(l0 - m), e1 = expf(l1 - m);
        float sum = e0 + e1;
        out[r*2]     = e0 / sum;
        out[r*2 + 1] = e1 / sum;
    }
}

// ---------------- launch sequence ----------------
extern "C" void kernel_launch(void* const* d_in, const int* in_sizes, int n_in,
                              void* d_out, int out_size) {
    const float* x      = (const float*)d_in[0];
    const int*   ei     = (const int*)  d_in[1];
    const float* Wrel1  = (const float*)d_in[2];
    const float* Wroot1 = (const float*)d_in[3];
    const float* b1     = (const float*)d_in[4];
    const float* Wrel2  = (const float*)d_in[5];
    const float* Wroot2 = (const float*)d_in[6];
    const float* b2     = (const float*)d_in[7];
    const float* Wrel3  = (const float*)d_in[8];
    const float* Wroot3 = (const float*)d_in[9];
    const float* b3     = (const float*)d_in[10];
    const float* pw1    = (const float*)d_in[11];
    const float* pw2    = (const float*)d_in[12];
    const float* pw3    = (const float*)d_in[13];
    const float* lin1_w = (const float*)d_in[14];
    const float* lin1_b = (const float*)d_in[15];
    const float* lin2_w = (const float*)d_in[16];
    const float* lin2_b = (const float*)d_in[17];
    const float* lin3_w = (const float*)d_in[18];
    const float* lin3_b = (const float*)d_in[19];
    const float* bn1_g  = (const float*)d_in[20];
    const float* bn1_b  = (const float*)d_in[21];
    const float* bn2_g  = (const float*)d_in[22];
    const float* bn2_b  = (const float*)d_in[23];
    float* out = (float*)d_out;

    // CSR build + init (single kernel)
    k_csr<<<G, 512>>>(ei, pw1, pw2, pw3);

    // level 1
    k_conv1f<<<NBLK, 256>>>(x, Wrel1, Wroot1, b1, pw1);
    k_rank<<<G, 512>>>(N0, K1);
    k_copy<<<NBLK, 256>>>(N0, K1, G*K1);
    k_rochunk<<<dim3(G, RCH), 128>>>(K1);
    k_zfin<<<G, 128>>>(K1, 1);
    k_gather<<<NBLK, 256>>>(G*K1);

    // level 2
    const int n2 = G * K1;
    k_convH<<<(n2 + 63)/64, 256>>>(n2, Wrel2, Wroot2, b2, pw2, 1);
    k_rank<<<G, 512>>>(K1, K2);
    k_copy<<<NBLK, 256>>>(K1, K2, G*K2);
    k_rochunk<<<dim3(G, RCH), 128>>>(K2);
    k_zfin<<<G, 128>>>(K2, 0);
    k_gather<<<NBLK, 256>>>(G*K2);

    // level 3
    const int n3 = G * K2;
    k_convH<<<(n3 + 63)/64, 256>>>(n3, Wrel3, Wroot3, b3, pw3, 2);
    k_rank<<<G, 512>>>(K2, K3);
    k_ro3<<<dim3(G, RCH), 128>>>(K2, K3);
    k_zfin<<<G, 128>>>(K3, 0);

    // MLP head
    k_fc1<<<dim3(16, 50), 256>>>(lin1_w, lin1_b);
    k_bn_relu<<<H, 64>>>(0, bn1_g, bn1_b);
    k_fc2<<<dim3(8, 25), 256>>>(lin2_w, lin2_b);
    k_bn_relu<<<64, 64>>>(1, bn2_g, bn2_b);
    k_final<<<(G + 127)/128, 128>>>(out, lin3_w, lin3_b);
}

// round 17
// speedup vs baseline: 1.3535x; 1.2225x over previous
#include <cuda_runtime.h>
#include <math.h>

#define G      200
#define N0     512
#define NN     (G*N0)        // 102400
#define DEG    6
#define ET     (G*N0*DEG)    // 614400
#define EPG    (N0*DEG)      // 3072 edges per graph
#define K1     410
#define K2     328
#define K3     263
#define FIN    6
#define H      128
#define EPS    1e-5f
#define NBLK   1184          // one-wave grid for stride kernels
#define RCH    16            // readout chunks per graph

typedef unsigned long long u64;

// ---------------- device scratch ----------------
__device__ float g_h  [NN*H];     // conv outputs (pre-pool)
__device__ float g_hn [NN*H];     // gated pooled features
__device__ float g_agg[NN*H];     // neighbor aggregation
__device__ float g_score[NN];
__device__ int   g_map[NN];
__device__ int   g_perm[NN];
__device__ int   g_sel[NN];
__device__ float g_gs[NN];
__device__ int   g_csr_off[NN+1];
__device__ int   g_csr_src[ET];
__device__ float g_z[G*2*H];
__device__ float g_zsum[G*H];
__device__ unsigned g_zmax[G*H];
__device__ float g_t1[G*H];
__device__ float g_t2[G*64];
__device__ float g_norm[3];
__device__ float g_whi[2][256*128];   // split weights, [k][n] layout
__device__ float g_wlo[2][256*128];

// ---------------- helpers ----------------
__device__ __forceinline__ unsigned fenc(float x) {
    unsigned u = __float_as_uint(x);
    return (u & 0x80000000u) ? ~u : (u | 0x80000000u);
}
__device__ __forceinline__ float fdec(unsigned e) {
    unsigned u = (e & 0x80000000u) ? (e & 0x7fffffffu) : ~e;
    return __uint_as_float(u);
}
__device__ __forceinline__ unsigned cvt_tf32(float x) {
    unsigned u; asm("cvt.rna.tf32.f32 %0,%1;" : "=r"(u) : "f"(x)); return u;
}
__device__ __forceinline__ void mma_tf32(float* c, unsigned a0, unsigned a1,
                                         unsigned a2, unsigned a3,
                                         unsigned b0, unsigned b1) {
    asm volatile(
        "mma.sync.aligned.m16n8k8.row.col.f32.tf32.tf32.f32 "
        "{%0,%1,%2,%3},{%4,%5,%6,%7},{%8,%9},{%0,%1,%2,%3};"
        : "+f"(c[0]), "+f"(c[1]), "+f"(c[2]), "+f"(c[3])
        : "r"(a0), "r"(a1), "r"(a2), "r"(a3), "r"(b0), "r"(b1));
}

// ------- CSR build + map init + pw norms ----------------
__global__ __launch_bounds__(512) void k_csr(const int* __restrict__ ei,
                                             const float* __restrict__ pw1,
                                             const float* __restrict__ pw2,
                                             const float* __restrict__ pw3) {
    int g = blockIdx.x;
    int tid = threadIdx.x;
    __shared__ int cnt[512];
    __shared__ int scur[512];
    int e0 = g * EPG;
    int nbase = g * N0;
    cnt[tid] = 0;
    __syncthreads();
    for (int i = tid; i < EPG; i += 512)
        atomicAdd(&cnt[ei[ET + e0 + i] - nbase], 1);
    __syncthreads();
    int v = cnt[tid];
    for (int off = 1; off < 512; off <<= 1) {
        int t = (tid >= off) ? cnt[tid - off] : 0;
        __syncthreads();
        cnt[tid] += t;
        __syncthreads();
    }
    int excl = cnt[tid] - v;
    g_csr_off[nbase + tid] = e0 + excl;
    scur[tid] = excl;
    if (g == 0 && tid == 0) g_csr_off[NN] = ET;
    g_map[nbase + tid] = nbase + tid;
    g_perm[nbase + tid] = nbase + tid;
    __syncthreads();
    for (int i = tid; i < EPG; i += 512) {
        int e = e0 + i;
        int d = ei[ET + e] - nbase;
        int idx = atomicAdd(&scur[d], 1);
        g_csr_src[e0 + idx] = ei[e];
    }
    if (g == 0) {
        __shared__ float sh[128];
        const float* pws[3] = {pw1, pw2, pw3};
        #pragma unroll
        for (int j = 0; j < 3; j++) {
            if (tid < 128) { float w = pws[j][tid]; sh[tid] = w * w; }
            __syncthreads();
            for (int s = 64; s > 0; s >>= 1) {
                if (tid < s) sh[tid] += sh[tid + s];
                __syncthreads();
            }
            if (tid == 0) g_norm[j] = sqrtf(sh[0]);
            __syncthreads();
        }
    }
}

// ------- weight split: fp32 -> tf32 hi/lo, [k][n] layout ----------------------
__global__ void k_wsplit(const float* __restrict__ Wroot2,
                         const float* __restrict__ Wrel2,
                         const float* __restrict__ Wroot3,
                         const float* __restrict__ Wrel3) {
    int idx = blockIdx.x * blockDim.x + threadIdx.x;   // 65536
    if (idx >= 2*256*128) return;
    int lvl = idx >> 15;
    int rem = idx & 32767;
    int k = rem >> 7;
    int nn = rem & 127;
    const float* Wroot = lvl ? Wroot3 : Wroot2;
    const float* Wrel  = lvl ? Wrel3  : Wrel2;
    float w = (k < 128) ? Wroot[nn*128 + k] : Wrel[nn*128 + (k - 128)];
    unsigned hi = cvt_tf32(w);
    float lo = w - __uint_as_float(hi);
    g_whi[lvl][k*128 + nn] = __uint_as_float(hi);
    g_wlo[lvl][k*128 + nn] = __uint_as_float(cvt_tf32(lo));
}

// ------- level 1: gather + conv(F_IN=6) + score; grid-stride ------------------
__global__ __launch_bounds__(256) void k_conv1f(
        const float* __restrict__ x,
        const float* __restrict__ Wrel,
        const float* __restrict__ Wroot,
        const float* __restrict__ b,
        const float* __restrict__ pw) {
    int sub = threadIdx.x >> 7;
    int o   = threadIdx.x & 127;
    __shared__ float sx[2][FIN], sa[2][FIN], sred[2][4];
    float nrm = g_norm[0];
    for (int node = blockIdx.x * 2 + sub; node < NN; node += gridDim.x * 2) {
        if (o < FIN) {
            sx[sub][o] = x[node*FIN + o];
            int s0 = g_csr_off[node], s1 = g_csr_off[node + 1];
            float acc = 0.0f;
            for (int i = s0; i < s1; i++) acc += x[g_csr_src[i]*FIN + o];
            sa[sub][o] = acc;
        }
        __syncthreads();
        float acc = b[o];
        #pragma unroll
        for (int f = 0; f < FIN; f++)
            acc += sa[sub][f] * Wrel[o*FIN + f] + sx[sub][f] * Wroot[o*FIN + f];
        float h = fmaxf(acc, 0.0f);
        g_h[node*H + o] = h;
        float p = h * pw[o];
        #pragma unroll
        for (int s = 16; s > 0; s >>= 1) p += __shfl_xor_sync(0xffffffffu, p, s);
        if ((o & 31) == 0) sred[sub][o >> 5] = p;
        __syncthreads();
        if (o == 0)
            g_score[node] = tanhf((sred[sub][0] + sred[sub][1] +
                                   sred[sub][2] + sred[sub][3]) / nrm);
        __syncthreads();
    }
}

// ------- H=128 conv via 3xTF32 tensor-core mma --------------------------------
// g_h = relu( g_hn@Wroot^T + g_agg@Wrel^T + b ); weights pre-split in g_whi/lo
__global__ __launch_bounds__(256) void k_convHt(int n, int lvl,
                                                const float* __restrict__ bias) {
    __shared__ float sAhi[16][136], sAlo[16][136];  // stride 136: banks 8k+c
    __shared__ float sBhi[16][132], sBlo[16][132];  // stride 132: banks 4k+c
    int tid  = threadIdx.x;
    int wid  = tid >> 5, lane = tid & 31;
    int wm   = wid >> 2;            // 0..1  (m64 halves)
    int wn   = wid & 3;             // 0..3  (n32 quarters)
    int gq   = lane >> 2;           // groupID 0..7
    int tig  = lane & 3;            // thread-in-group
    int m0   = blockIdx.x * 128;
    const float* whi = g_whi[lvl];
    const float* wlo = g_wlo[lvl];

    float acc[4][4][4];
    #pragma unroll
    for (int mi = 0; mi < 4; mi++)
        #pragma unroll
        for (int ni = 0; ni < 4; ni++)
            #pragma unroll
            for (int q = 0; q < 4; q++) acc[mi][ni][q] = 0.0f;

    for (int kt = 0; kt < 256; kt += 16) {
        const float* asrc = (kt < 128) ? g_hn : g_agg;
        int kb = kt & 127;
        // stage A: 128 nodes x 16 k, split to tf32 hi/lo
        #pragma unroll
        for (int l = 0; l < 2; l++) {
            int idx = tid + l * 256;        // 0..511
            int node = idx >> 2;
            int k4 = (idx & 3) * 4;
            int gn = m0 + node;
            float4 v = make_float4(0.f, 0.f, 0.f, 0.f);
            if (gn < n) v = *(const float4*)&asrc[gn*H + kb + k4];
            float vv[4] = {v.x, v.y, v.z, v.w};
            #pragma unroll
            for (int i = 0; i < 4; i++) {
                unsigned hi = cvt_tf32(vv[i]);
                float lo = vv[i] - __uint_as_float(hi);
                sAhi[k4 + i][node] = __uint_as_float(hi);
                sAlo[k4 + i][node] = __uint_as_float(cvt_tf32(lo));
            }
        }
        // stage B: 16 k x 128 n (already tf32 patterns; straight copy)
        #pragma unroll
        for (int l = 0; l < 2; l++) {
            int idx = tid + l * 256;        // 0..511 float4s
            int kk = idx >> 5;
            int c4 = (idx & 31) * 4;
            *(float4*)&sBhi[kk][c4] = *(const float4*)&whi[(kt + kk)*128 + c4];
            *(float4*)&sBlo[kk][c4] = *(const float4*)&wlo[(kt + kk)*128 + c4];
        }
        __syncthreads();
        #pragma unroll
        for (int k8 = 0; k8 < 16; k8 += 8) {
            // B fragments for all 4 n-tiles
            unsigned bh[4][2], bl[4][2];
            #pragma unroll
            for (int ni = 0; ni < 4; ni++) {
                int cb = wn*32 + ni*8 + gq;
                bh[ni][0] = __float_as_uint(sBhi[k8 + tig][cb]);
                bh[ni][1] = __float_as_uint(sBhi[k8 + tig + 4][cb]);
                bl[ni][0] = __float_as_uint(sBlo[k8 + tig][cb]);
                bl[ni][1] = __float_as_uint(sBlo[k8 + tig + 4][cb]);
            }
            #pragma unroll
            for (int mi = 0; mi < 4; mi++) {
                int rb = wm*64 + mi*16 + gq;
                unsigned ah0 = __float_as_uint(sAhi[k8 + tig][rb]);
                unsigned ah1 = __float_as_uint(sAhi[k8 + tig][rb + 8]);
                unsigned ah2 = __float_as_uint(sAhi[k8 + tig + 4][rb]);
                unsigned ah3 = __float_as_uint(sAhi[k8 + tig + 4][rb + 8]);
                unsigned al0 = __float_as_uint(sAlo[k8 + tig][rb]);
                unsigned al1 = __float_as_uint(sAlo[k8 + tig][rb + 8]);
                unsigned al2 = __float_as_uint(sAlo[k8 + tig + 4][rb]);
                unsigned al3 = __float_as_uint(sAlo[k8 + tig + 4][rb + 8]);
                #pragma unroll
                for (int ni = 0; ni < 4; ni++) {
                    mma_tf32(acc[mi][ni], ah0, ah1, ah2, ah3, bh[ni][0], bh[ni][1]);
                    mma_tf32(acc[mi][ni], ah0, ah1, ah2, ah3, bl[ni][0], bl[ni][1]);
                    mma_tf32(acc[mi][ni], al0, al1, al2, al3, bh[ni][0], bh[ni][1]);
                }
            }
        }
        __syncthreads();
    }
    // epilogue: bias + relu + store
    #pragma unroll
    for (int mi = 0; mi < 4; mi++) {
        int row0 = m0 + wm*64 + mi*16 + gq;
        int row1 = row0 + 8;
        #pragma unroll
        for (int ni = 0; ni < 4; ni++) {
            int col0 = wn*32 + ni*8 + 2*tig;
            float b0v = bias[col0], b1v = bias[col0 + 1];
            if (row0 < n) {
                float2 o;
                o.x = fmaxf(acc[mi][ni][0] + b0v, 0.0f);
                o.y = fmaxf(acc[mi][ni][1] + b1v, 0.0f);
                *(float2*)&g_h[row0*H + col0] = o;
            }
            if (row1 < n) {
                float2 o;
                o.x = fmaxf(acc[mi][ni][2] + b0v, 0.0f);
                o.y = fmaxf(acc[mi][ni][3] + b1v, 0.0f);
                *(float2*)&g_h[row1*H + col0] = o;
            }
        }
    }
}

// ------- scores from g_h (fp32 exact): warp per node --------------------------
__global__ __launch_bounds__(256) void k_score(int n, const float* __restrict__ pw,
                                               int which) {
    int slot = threadIdx.x >> 5, lane = threadIdx.x & 31;
    float nrm = g_norm[which];
    float4 pw4 = *(const float4*)&pw[lane*4];
    for (int node = blockIdx.x * 8 + slot; node < n; node += gridDim.x * 8) {
        float4 h4 = *(const float4*)&g_h[node*H + lane*4];
        float p = h4.x*pw4.x + h4.y*pw4.y + h4.z*pw4.z + h4.w*pw4.w;
        #pragma unroll
        for (int s = 16; s > 0; s >>= 1) p += __shfl_xor_sync(0xffffffffu, p, s);
        if (lane == 0) g_score[node] = tanhf(p / nrm);
    }
}

// ------ rank: stable top-k + compose + sel + init readout accum --------------
__global__ void k_rank(int n_per, int k) {
    int g = blockIdx.x;
    int tid = threadIdx.x;
    __shared__ float s[512];
    __shared__ int   rk[512];
    if (tid < n_per) s[tid] = g_score[g*n_per + tid];
    if (tid < H) {
        g_zsum[g*H + tid] = 0.0f;
        g_zmax[g*H + tid] = fenc(-INFINITY);
    }
    __syncthreads();
    if (tid < n_per) {
        float si = s[tid];
        int r = 0;
        for (int j = 0; j < n_per; j++) {
            float sj = s[j];
            r += (sj > si) || (sj == si && j < tid);
        }
        rk[tid] = r;
        if (r < k) { g_sel[g*k + r] = tid; g_gs[g*k + r] = si; }
    }
    __syncthreads();
    int orig = g*N0 + tid;
    int c = g_map[orig];
    int nc = -1;
    if (c >= 0) {
        int r = rk[c - g*n_per];
        nc = (r < k) ? (g*k + r) : -1;
    }
    g_map[orig] = nc;
    if (nc >= 0) g_perm[nc] = orig;
}

// ------- gated copy: warp-per-node, float4 -----------------------------------
__global__ __launch_bounds__(256) void k_copy(int n_per, int k, int n) {
    int slot = threadIdx.x >> 5;
    int lane = threadIdx.x & 31;
    for (int j = blockIdx.x * 8 + slot; j < n; j += gridDim.x * 8) {
        int g = j / k;
        int old = g * n_per + g_sel[j];
        float gs = g_gs[j];
        float4 v = *(const float4*)&g_h[old*H + lane*4];
        v.x *= gs; v.y *= gs; v.z *= gs; v.w *= gs;
        *(float4*)&g_hn[j*H + lane*4] = v;
    }
}

// ------- chunked dense readout ------------------------------------------------
__global__ __launch_bounds__(128) void k_rochunk(int k) {
    int g = blockIdx.x, c = blockIdx.y;
    int f = threadIdx.x;
    float mx = -INFINITY, sm = 0.0f;
    for (int r = c; r < k; r += RCH) {
        float v = g_hn[(g*k + r)*H + f];
        mx = fmaxf(mx, v);
        sm += v;
    }
    atomicMax(&g_zmax[g*H + f], fenc(mx));
    atomicAdd(&g_zsum[g*H + f], sm);
}

// ------- level-3 chunked gated readout ----------------------------------------
__global__ __launch_bounds__(128) void k_ro3(int n_per, int k) {
    int g = blockIdx.x, c = blockIdx.y;
    int f = threadIdx.x;
    int base = g * n_per;
    float mx = -INFINITY, sm = 0.0f;
    for (int r = c; r < k; r += RCH) {
        int j = g*k + r;
        float v = g_h[(base + g_sel[j])*H + f] * g_gs[j];
        mx = fmaxf(mx, v);
        sm += v;
    }
    atomicMax(&g_zmax[g*H + f], fenc(mx));
    atomicAdd(&g_zsum[g*H + f], sm);
}

// ------- finalize readout ------------------------------------------------------
__global__ void k_zfin(int k, int store_z) {
    int g = blockIdx.x, f = threadIdx.x;
    float mx = fdec(g_zmax[g*H + f]);
    float mn = g_zsum[g*H + f] / (float)k;
    if (store_z) { g_z[g*2*H + f] = mx;  g_z[g*2*H + H + f] = mn; }
    else         { g_z[g*2*H + f] += mx; g_z[g*2*H + H + f] += mn; }
}

// ------- gather: warp-per-node, shfl-broadcast rows, float4 -------------------
__global__ __launch_bounds__(256) void k_gather(int n) {
    int slot = threadIdx.x >> 5;
    int lane = threadIdx.x & 31;
    for (int v = blockIdx.x * 8 + slot; v < n; v += gridDim.x * 8) {
        int u = g_perm[v];
        int start = g_csr_off[u];
        int deg   = g_csr_off[u + 1] - start;
        int row = -1;
        if (lane < deg) {
            int w = g_map[g_csr_src[start + lane]];
            row = (w >= 0) ? w * H : -1;
        }
        float4 acc = make_float4(0.f, 0.f, 0.f, 0.f);
        int m = deg < 32 ? deg : 32;
        for (int i = 0; i < m; i++) {
            int r = __shfl_sync(0xffffffffu, row, i);
            if (r >= 0) {
                float4 t = *(const float4*)&g_hn[r + lane*4];
                acc.x += t.x; acc.y += t.y; acc.z += t.z; acc.w += t.w;
            }
        }
        for (int i = 32; i < deg; i++) {
            int w = g_map[g_csr_src[start + i]];
            if (w >= 0) {
                float4 t = *(const float4*)&g_hn[w*H + lane*4];
                acc.x += t.x; acc.y += t.y; acc.z += t.z; acc.w += t.w;
            }
        }
        *(float4*)&g_agg[v*H + lane*4] = acc;
    }
}

// ---------------- MLP head ----------------
__global__ void k_fc1(const float* __restrict__ W, const float* __restrict__ b) {
    int w = threadIdx.x >> 5, lane = threadIdx.x & 31;
    int o = blockIdx.x * 8 + w;
    int r0 = blockIdx.y * 4;
    const float* Wo = &W[o*2*H];
    float wreg[8];
    #pragma unroll
    for (int i = 0; i < 8; i++) wreg[i] = Wo[lane + 32*i];
    #pragma unroll
    for (int rr = 0; rr < 4; rr++) {
        int r = r0 + rr;
        const float* zr = &g_z[r*2*H];
        float acc = 0.0f;
        #pragma unroll
        for (int i = 0; i < 8; i++) acc += zr[lane + 32*i] * wreg[i];
        #pragma unroll
        for (int s = 16; s > 0; s >>= 1) acc += __shfl_xor_sync(0xffffffffu, acc, s);
        if (lane == 0) g_t1[r*H + o] = acc + b[o];
    }
}
__global__ void k_fc2(const float* __restrict__ W, const float* __restrict__ b) {
    int w = threadIdx.x >> 5, lane = threadIdx.x & 31;
    int o = blockIdx.x * 8 + w;
    int r0 = blockIdx.y * 8;
    const float* Wo = &W[o*H];
    float wreg[4];
    #pragma unroll
    for (int i = 0; i < 4; i++) wreg[i] = Wo[lane + 32*i];
    #pragma unroll
    for (int rr = 0; rr < 8; rr++) {
        int r = r0 + rr;
        const float* tr = &g_t1[r*H];
        float acc = 0.0f;
        #pragma unroll
        for (int i = 0; i < 4; i++) acc += tr[lane + 32*i] * wreg[i];
        #pragma unroll
        for (int s = 16; s > 0; s >>= 1) acc += __shfl_xor_sync(0xffffffffu, acc, s);
        if (lane == 0) g_t2[r*64 + o] = acc + b[o];
    }
}
__global__ void k_bn_relu(int sel, const float* __restrict__ gam,
                          const float* __restrict__ bet) {
    int F = sel ? 64 : H;
    float* Xp = sel ? g_t2 : g_t1;
    int f = blockIdx.x;
    int t = threadIdx.x;
    __shared__ float sh[64];
    float s = 0.0f;
    for (int r = t; r < G; r += 64) s += Xp[r*F + f];
    sh[t] = s; __syncthreads();
    for (int st = 32; st > 0; st >>= 1) { if (t < st) sh[t] += sh[t + st]; __syncthreads(); }
    float mean = sh[0] / (float)G;
    __syncthreads();
    float v = 0.0f;
    for (int r = t; r < G; r += 64) { float d = Xp[r*F + f] - mean; v += d * d; }
    sh[t] = v; __syncthreads();
    for (int st = 32; st > 0; st >>= 1) { if (t < st) sh[t] += sh[t + st]; __syncthreads(); }
    float inv = 1.0f / sqrtf(sh[0] / (float)G + EPS);
    float gg = gam[f], bb = bet[f];
    for (int r = t; r < G; r += 64) {
        float y = (Xp[r*F + f] - mean) * inv * gg + bb;
        Xp[r*F + f] = fmaxf(y, 0.0f);
    }
}
__global__ void k_final(float* __restrict__ out,
                        const float* __restrict__ W,
                        const float* __restrict__ b) {
    int r = blockIdx.x * blockDim.x + threadIdx.x;
    if (r < G) {
        float l0 = b[0], l1 = b[1];
        for (int f = 0; f < 64; f++) {
            float v = g_t2[r*64 + f];
            l0 += v * W[f];
            l1 += v * W[64 + f];
        }
        float m = fmaxf(l0, l1);
        float e0 = expf(l0 - m), e1 = expf(l1 - m);
        float sum = e0 + e1;
        out[r*2]     = e0 / sum;
        out[r*2 + 1] = e1 / sum;
    }
}

// ---------------- launch sequence ----------------
extern "C" void kernel_launch(void* const* d_in, const int* in_sizes, int n_in,
                              void* d_out, int out_size) {
    const float* x      = (const float*)d_in[0];
    const int*   ei     = (const int*)  d_in[1];
    const float* Wrel1  = (const float*)d_in[2];
    const float* Wroot1 = (const float*)d_in[3];
    const float* b1     = (const float*)d_in[4];
    const float* Wrel2  = (const float*)d_in[5];
    const float* Wroot2 = (const float*)d_in[6];
    const float* b2     = (const float*)d_in[7];
    const float* Wrel3  = (const float*)d_in[8];
    const float* Wroot3 = (const float*)d_in[9];
    const float* b3     = (const float*)d_in[10];
    const float* pw1    = (const float*)d_in[11];
    const float* pw2    = (const float*)d_in[12];
    const float* pw3    = (const float*)d_in[13];
    const float* lin1_w = (const float*)d_in[14];
    const float* lin1_b = (const float*)d_in[15];
    const float* lin2_w = (const float*)d_in[16];
    const float* lin2_b = (const float*)d_in[17];
    const float* lin3_w = (const float*)d_in[18];
    const float* lin3_b = (const float*)d_in[19];
    const float* bn1_g  = (const float*)d_in[20];
    const float* bn1_b  = (const float*)d_in[21];
    const float* bn2_g  = (const float*)d_in[22];
    const float* bn2_b  = (const float*)d_in[23];
    float* out = (float*)d_out;

    k_csr<<<G, 512>>>(ei, pw1, pw2, pw3);
    k_wsplit<<<(2*256*128 + 255)/256, 256>>>(Wroot2, Wrel2, Wroot3, Wrel3);

    // level 1
    k_conv1f<<<NBLK, 256>>>(x, Wrel1, Wroot1, b1, pw1);
    k_rank<<<G, 512>>>(N0, K1);
    k_copy<<<NBLK, 256>>>(N0, K1, G*K1);
    k_rochunk<<<dim3(G, RCH), 128>>>(K1);
    k_zfin<<<G, 128>>>(K1, 1);
    k_gather<<<NBLK, 256>>>(G*K1);

    // level 2
    const int n2 = G * K1;
    k_convHt<<<(n2 + 127)/128, 256>>>(n2, 0, b2);
    k_score<<<NBLK, 256>>>(n2, pw2, 1);
    k_rank<<<G, 512>>>(K1, K2);
    k_copy<<<NBLK, 256>>>(K1, K2, G*K2);
    k_rochunk<<<dim3(G, RCH), 128>>>(K2);
    k_zfin<<<G, 128>>>(K2, 0);
    k_gather<<<NBLK, 256>>>(G*K2);

    // level 3
    const int n3 = G * K2;
    k_convHt<<<(n3 + 127)/128, 256>>>(n3, 1, b3);
    k_score<<<NBLK, 256>>>(n3, pw3, 2);
    k_rank<<<G, 512>>>(K2, K3);
    k_ro3<<<dim3(G, RCH), 128>>>(K2, K3);
    k_zfin<<<G, 128>>>(K3, 0);

    // MLP head
    k_fc1<<<dim3(16, 50), 256>>>(lin1_w, lin1_b);
    k_bn_relu<<<H, 64>>>(0, bn1_g, bn1_b);
    k_fc2<<<dim3(8, 25), 256>>>(lin2_w, lin2_b);
    k_bn_relu<<<64, 64>>>(1, bn2_g, bn2_b);
    k_final<<<(G + 127)/128, 128>>>(out, lin3_w, lin3_b);
}